// round 17
// baseline (speedup 1.0000x reference)
#include <cuda_runtime.h>
#include <cuda_bf16.h>
#include <cstdint>

// ----------------------------------------------------------------------------
// RadianceRenderer R17: R16 + accumulator RAW chains broken: (a) lo*hi product
// goes into a SEPARATE accumulator (merged with 1 FADD at consumer), (b) MMAs
// issued product-major so consecutive MMAs never share an accumulator.
// Grid = 296 persistent blocks, 256 threads, 2 rays/iteration.
// ----------------------------------------------------------------------------

typedef unsigned long long ull;
typedef unsigned int u32;

#define GRID 296
#define N_PAIRS 4096   // 8192 rays / 2

// fragment-ordered B operands in GLOBAL (verified packing):
// uint4 = {hi(k0,k0+1), hi(k0+8,k0+9), lo.., lo..}; [tile][lane].
// W2 @0 (128), feat @4096 (24), c1 @4864 (32), c2 @5888 (8).
__device__ __align__(16) uint4 g_Bf[6144];

__device__ __forceinline__ void cpa16(u32 dst, const void* src) {
    asm volatile("cp.async.ca.shared.global [%0], [%1], 16;" :: "r"(dst), "l"(src));
}
__device__ __forceinline__ void cpa_commit() {
    asm volatile("cp.async.commit_group;" ::: "memory");
}
template <int N>
__device__ __forceinline__ void cpa_wait() {
    asm volatile("cp.async.wait_group %0;" :: "n"(N) : "memory");
}
__device__ __forceinline__ u32 smem_u32(const void* p) {
    return (u32)__cvta_generic_to_shared(p);
}
__device__ __forceinline__ void bar_slot(int slot) {
    asm volatile("bar.sync %0, 128;" :: "r"(slot + 1) : "memory");
}

__device__ __forceinline__ void mma16816(float c[4], const u32 a[4], u32 b0, u32 b1) {
    asm volatile(
        "mma.sync.aligned.m16n8k16.row.col.f32.bf16.bf16.f32 "
        "{%0,%1,%2,%3}, {%4,%5,%6,%7}, {%8,%9}, {%0,%1,%2,%3};"
        : "+f"(c[0]), "+f"(c[1]), "+f"(c[2]), "+f"(c[3])
        : "r"(a[0]), "r"(a[1]), "r"(a[2]), "r"(a[3]), "r"(b0), "r"(b1));
}

// fast split: hi = {bf16(v1)|bf16(v0)}, lo = residuals, via packed cvt
__device__ __forceinline__ void split_pack(float v0, float v1, u32& hi, u32& lo) {
    u32 h;
    asm("cvt.rn.bf16x2.f32 %0, %1, %2;" : "=r"(h) : "f"(v1), "f"(v0));
    float f0 = __uint_as_float(h << 16);
    float f1 = __uint_as_float(h & 0xFFFF0000u);
    u32 l;
    asm("cvt.rn.bf16x2.f32 %0, %1, %2;" : "=r"(l) : "f"(v1 - f1), "f"(v0 - f0));
    hi = h;
    lo = l;
}

__device__ __forceinline__ float fast_sigmoid(float x) {
    return 1.f / (1.f + __expf(-x));
}

// ---------- prep: pack all B operands fragment-ordered (verified) ----------
__global__ void prep_all(const float* __restrict__ W2, const float* __restrict__ Wf,
                         const float* __restrict__ Wd, const float* __restrict__ Wc1,
                         const float* __restrict__ Wc2) {
    int b = blockIdx.x;
    int lane = threadIdx.x;
    int kq = (lane & 3) * 2, nq = lane >> 2;
    float x0, x1, x2, x3;
    uint4* dst;
    if (b < 128) {
        int ks = b >> 4, nt = b & 15;
        int k0 = ks * 16 + kq, n = nt * 8 + nq;
        x0 = W2[k0 * 128 + n];
        x1 = W2[(k0 + 1) * 128 + n];
        x2 = W2[(k0 + 8) * 128 + n];
        x3 = W2[(k0 + 9) * 128 + n];
        dst = g_Bf + b * 32 + lane;
    } else if (b < 152) {
        int idx = b - 128, ks = idx / 3, nt = idx - ks * 3;
        int k0 = ks * 16 + kq, n = nt * 8 + nq;
        auto val = [&](int k) -> float {
            if (n < 16) return Wf[k * 16 + n];
            if (n == 16) return Wd[k];
            return 0.f;
        };
        x0 = val(k0); x1 = val(k0 + 1); x2 = val(k0 + 8); x3 = val(k0 + 9);
        dst = g_Bf + 4096 + idx * 32 + lane;
    } else if (b < 184) {
        int idx = b - 152, ks = idx >> 4, nt = idx & 15;
        int k0 = ks * 16 + kq, n = nt * 8 + nq;
        x0 = Wc1[k0 * 128 + n];
        x1 = Wc1[(k0 + 1) * 128 + n];
        x2 = Wc1[(k0 + 8) * 128 + n];
        x3 = Wc1[(k0 + 9) * 128 + n];
        dst = g_Bf + 4864 + idx * 32 + lane;
    } else {
        int ks = b - 184;
        int k0 = ks * 16 + kq, n = nq;
        auto val = [&](int k) -> float { return (n < 3) ? Wc2[k * 3 + n] : 0.f; };
        x0 = val(k0); x1 = val(k0 + 1); x2 = val(k0 + 8); x3 = val(k0 + 9);
        dst = g_Bf + 5888 + ks * 32 + lane;
    }
    uint4 v;
    split_pack(x0, x1, v.x, v.z);
    split_pack(x2, x3, v.y, v.w);
    *dst = v;
}

// smem floats: sB uint4 [0,22528)=90112B; wsm 22528..23328; wy 23328..25376;
// per-slot (x2): sxyz 25376(192ea) sts 25760(64) ssig 25888(64) sins 26016(64)
// synm 26144(16) sc0 26176(64) sc1 26304(64) sc2 26432(64) sred 26560(16)
// shcY 26592(128). total 26848 fl = 107392 B -> 2 blocks/SM.
__global__ __launch_bounds__(256, 2) void radiance_kernel(
    const float* __restrict__ rays_o, const float* __restrict__ rays_d,
    const float* __restrict__ aabb,
    const float* __restrict__ W1, const float* __restrict__ b1,
    const float* __restrict__ W2, const float* __restrict__ b2,
    const float* __restrict__ Wd, const float* __restrict__ bd,
    const float* __restrict__ Wf, const float* __restrict__ bf,
    const float* __restrict__ Wc1, const float* __restrict__ bc1,
    const float* __restrict__ Wc2, const float* __restrict__ bc2,
    float* __restrict__ out) {
    extern __shared__ float sm[];
    const uint4* sB = (const uint4*)sm;
    float* wsm = sm + 22528;
    float* wy  = sm + 23328;

    const int tid = threadIdx.x;
    const int lane = tid & 31;
    const int wid = tid >> 5;
    const int slot = tid >> 7;
    const int t128 = tid & 127;
    const int lwid = wid & 3;
    const int pb = lwid * 16;
    const int r0 = lane >> 2;
    const int p0 = pb + r0, p1 = p0 + 8;
    const int kq = (lane & 3) * 2;
    const u32 sBu = smem_u32(sm);

    float* sxyz_s = sm + 25376 + slot * 192;
    float* sts_s  = sm + 25760 + slot * 64;
    float* ssig_s = sm + 25888 + slot * 64;
    float* sins_s = sm + 26016 + slot * 64;
    float* synm_s = sm + 26144 + slot * 16;
    float* sc0_s  = sm + 26176 + slot * 64;
    float* sc1_s  = sm + 26304 + slot * 64;
    float* sc2_s  = sm + 26432 + slot * 64;
    float* sred_s = sm + 26560 + slot * 16;
    float* shcY_s = sm + 26592 + slot * 128;

    // ---- one-time staging (256 threads) ----
    {
#pragma unroll
        for (int i = 0; i < 16; i++)
            cpa16(sBu + (u32)(tid + i * 256) * 16u, g_Bf + tid + i * 256);
#pragma unroll
        for (int i = 0; i < 3; i++)
            cpa16(sBu + (u32)(4096 + tid + i * 256) * 16u, g_Bf + 4096 + tid + i * 256);
#pragma unroll
        for (int i = 0; i < 2; i++)
            cpa16(sBu + (u32)(4864 + tid + i * 256) * 16u, g_Bf + 4864 + tid + i * 256);
        cpa16(sBu + (u32)(5376 + tid) * 16u, g_Bf + 5888 + tid);
        u32 wu = smem_u32(wsm);
        if (tid < 96) cpa16(wu + tid * 16u, W1 + tid * 4);
        else if (tid < 128) cpa16(wu + 1536u + (tid - 96) * 16u, b1 + (tid - 96) * 4);
        else if (tid < 160) cpa16(wu + 2048u + (tid - 128) * 16u, b2 + (tid - 128) * 4);
        else if (tid < 192) cpa16(wu + 2560u + (tid - 160) * 16u, bc1 + (tid - 160) * 4);
        else if (tid < 196) cpa16(wu + 3072u + (tid - 192) * 16u, bf + (tid - 192) * 4);
        u32 wyu = smem_u32(wy);
#pragma unroll
        for (int i = 0; i < 2; i++)
            cpa16(wyu + (u32)(tid + i * 256) * 16u, Wc1 + 2048 + (tid + i * 256) * 4);
        cpa_commit();
        if (tid == 200) wsm[784] = __ldg(bd);
        if (tid >= 201 && tid < 204) wsm[785 + tid - 201] = __ldg(bc2 + tid - 201);
    }
    float a0x = aabb[0], a0y = aabb[1], a0z = aabb[2];
    float a1x = aabb[3], a1y = aabb[4], a1z = aabb[5];
    cpa_wait<0>();
    __syncthreads();  // block-wide: staging complete

    // ================= per-ray-pair loop (slots free-run) =================
#pragma unroll 1
    for (int pr = blockIdx.x; pr < N_PAIRS; pr += GRID) {
        const int ray = pr * 2 + slot;
        float ox = rays_o[ray * 3 + 0], oy = rays_o[ray * 3 + 1], oz = rays_o[ray * 3 + 2];
        float dx = rays_d[ray * 3 + 0], dy = rays_d[ray * 3 + 1], dz = rays_d[ray * 3 + 2];
        float ix = 1.f / dx, iy = 1.f / dy, iz = 1.f / dz;
        float t1x = (a0x - ox) * ix, t2x = (a1x - ox) * ix;
        float t1y = (a0y - oy) * iy, t2y = (a1y - oy) * iy;
        float t1z = (a0z - oz) * iz, t2z = (a1z - oz) * iz;
        float tn = fmaxf(fmaxf(fminf(t1x, t2x), fminf(t1y, t2y)), fminf(t1z, t2z));
        tn = fmaxf(tn, 0.f);
        float tf = fminf(fminf(fmaxf(t1x, t2x), fmaxf(t1y, t2y)), fmaxf(t1z, t2z));
        tf = fminf(tf, 10.f);
        bool active = tn < tf;
        if (!active) { tn = 0.f; tf = 1.f; }
        float dnorm = sqrtf(dx * dx + dy * dy + dz * dz);

        if (t128 == 0) {
            float inv = 1.f / dnorm;
            float x = dx * inv, y = dy * inv, z = dz * inv;
            float x2 = x * x, y2 = y * y, z2 = z * z;
            synm_s[0]  = 0.282094791773878f;
            synm_s[1]  = -0.488602511902920f * y;
            synm_s[2]  = 0.488602511902920f * z;
            synm_s[3]  = -0.488602511902920f * x;
            synm_s[4]  = 1.092548430592079f * x * y;
            synm_s[5]  = -1.092548430592079f * y * z;
            synm_s[6]  = 0.315391565252520f * (3.0f * z2 - 1.0f);
            synm_s[7]  = -1.092548430592079f * x * z;
            synm_s[8]  = 0.546274215296040f * (x2 - y2);
            synm_s[9]  = -0.590043589926644f * y * (3.0f * x2 - y2);
            synm_s[10] = 2.890611442640554f * x * y * z;
            synm_s[11] = -0.457045799464466f * y * (5.0f * z2 - 1.0f);
            synm_s[12] = 0.373176332590115f * z * (5.0f * z2 - 3.0f);
            synm_s[13] = -0.457045799464466f * x * (5.0f * z2 - 1.0f);
            synm_s[14] = 1.445305721320277f * z * (x2 - y2);
            synm_s[15] = -0.590043589926644f * x * (x2 - 3.0f * y2);
        }
        if (t128 < 64) {
            float fr = (t128 + 0.5f) * (1.f / 64.f);
            float t = tn + fr * (tf - tn);
            sts_s[t128] = t;
            float px = fmaf(dx, t, ox), py = fmaf(dy, t, oy), pz = fmaf(dz, t, oz);
            float nx = (px - a0x) / (a1x - a0x) * 2.f - 1.f;
            float ny = (py - a0y) / (a1y - a0y) * 2.f - 1.f;
            float nz = (pz - a0z) / (a1z - a0z) * 2.f - 1.f;
            sxyz_s[t128 * 3 + 0] = nx;
            sxyz_s[t128 * 3 + 1] = ny;
            sxyz_s[t128 * 3 + 2] = nz;
            bool inside = (nx >= -1.f) && (nx <= 1.f) && (ny >= -1.f) && (ny <= 1.f) &&
                          (nz >= -1.f) && (nz <= 1.f);
            sins_s[t128] = inside ? 1.f : 0.f;
        }
        bar_slot(slot);  // (1) setup visible

        // hcY: point-invariant (ynm @ Wc1) + bc1 folded in
        {
            float acc = wsm[640 + t128];  // bc1
#pragma unroll
            for (int j = 0; j < 16; j++)
                acc = fmaf(synm_s[j], wy[j * 128 + t128], acc);
            shcY_s[t128] = acc;
        }
        bar_slot(slot);  // (1b) shcY visible

        float P0x = sxyz_s[p0 * 3], P0y = sxyz_s[p0 * 3 + 1], P0z = sxyz_s[p0 * 3 + 2];
        float P1x = sxyz_s[p1 * 3], P1y = sxyz_s[p1 * 3 + 1], P1z = sxyz_s[p1 * 3 + 2];

        // ======== build W2 A-fragments ONCE (AH/AL[8][4]) ========
        u32 AH[8][4], AL[8][4];
#pragma unroll
        for (int ks = 0; ks < 8; ks++) {
            int j0 = ks * 16 + kq;
            float v[8];
#pragma unroll
            for (int q = 0; q < 4; q++) {
                int j = j0 + (q & 1) + (q >> 1) * 8;
                float w0 = wsm[j], w1 = wsm[128 + j], w2 = wsm[256 + j];
                float bb = wsm[384 + j];
                float h0 = fmaf(P0x, w0, bb);
                h0 = fmaf(P0y, w1, h0);
                h0 = fmaf(P0z, w2, h0);
                float h1v = fmaf(P1x, w0, bb);
                h1v = fmaf(P1y, w1, h1v);
                h1v = fmaf(P1z, w2, h1v);
                v[q] = fmaxf(h0, 0.f);
                v[4 + q] = fmaxf(h1v, 0.f);
            }
            split_pack(v[0], v[1], AH[ks][0], AL[ks][0]);
            split_pack(v[4], v[5], AH[ks][1], AL[ks][1]);
            split_pack(v[2], v[3], AH[ks][2], AL[ks][2]);
            split_pack(v[6], v[7], AH[ks][3], AL[ks][3]);
        }

        // ======== W2 in 4 N-quarters, dual accumulators, product-major ========
        float cf[3][4], cfl[3][4];
#pragma unroll
        for (int nt = 0; nt < 3; nt++)
#pragma unroll
            for (int i = 0; i < 4; i++) { cf[nt][i] = 0.f; cfl[nt][i] = 0.f; }

#pragma unroll
        for (int qt = 0; qt < 4; qt++) {
            float c[4][4], cl[4][4];
#pragma unroll
            for (int nt = 0; nt < 4; nt++)
#pragma unroll
                for (int i = 0; i < 4; i++) { c[nt][i] = 0.f; cl[nt][i] = 0.f; }
#pragma unroll
            for (int ks = 0; ks < 8; ks++) {
                const uint4* gb = sB + (ks * 16 + qt * 4) * 32 + lane;
                uint4 B0 = gb[0], B1 = gb[32], B2 = gb[64], B3 = gb[96];
                mma16816(c[0], AH[ks], B0.x, B0.y);
                mma16816(c[1], AH[ks], B1.x, B1.y);
                mma16816(c[2], AH[ks], B2.x, B2.y);
                mma16816(c[3], AH[ks], B3.x, B3.y);
                mma16816(cl[0], AL[ks], B0.x, B0.y);
                mma16816(cl[1], AL[ks], B1.x, B1.y);
                mma16816(cl[2], AL[ks], B2.x, B2.y);
                mma16816(cl[3], AL[ks], B3.x, B3.y);
                mma16816(c[0], AH[ks], B0.z, B0.w);
                mma16816(c[1], AH[ks], B1.z, B1.w);
                mma16816(c[2], AH[ks], B2.z, B2.w);
                mma16816(c[3], AH[ks], B3.z, B3.w);
            }
            // feat consumer: this quarter's h2 cols = feat k-chunks 2qt, 2qt+1
#pragma unroll
            for (int j = 0; j < 2; j++) {
                int ksf = qt * 2 + j;
                int col = ksf * 16 + kq;
                float b20 = wsm[512 + col], b21 = wsm[512 + col + 1];
                float b28 = wsm[512 + col + 8], b29 = wsm[512 + col + 9];
                u32 ahi[4], alo[4];
                split_pack(fmaxf(c[2 * j][0] + cl[2 * j][0] + b20, 0.f),
                           fmaxf(c[2 * j][1] + cl[2 * j][1] + b21, 0.f), ahi[0], alo[0]);
                split_pack(fmaxf(c[2 * j][2] + cl[2 * j][2] + b20, 0.f),
                           fmaxf(c[2 * j][3] + cl[2 * j][3] + b21, 0.f), ahi[1], alo[1]);
                split_pack(fmaxf(c[2 * j + 1][0] + cl[2 * j + 1][0] + b28, 0.f),
                           fmaxf(c[2 * j + 1][1] + cl[2 * j + 1][1] + b29, 0.f),
                           ahi[2], alo[2]);
                split_pack(fmaxf(c[2 * j + 1][2] + cl[2 * j + 1][2] + b28, 0.f),
                           fmaxf(c[2 * j + 1][3] + cl[2 * j + 1][3] + b29, 0.f),
                           ahi[3], alo[3]);
                const uint4* gb = sB + 4096 + ksf * 3 * 32 + lane;
                uint4 F0 = gb[0], F1 = gb[32], F2 = gb[64];
                mma16816(cf[0], ahi, F0.x, F0.y);
                mma16816(cf[1], ahi, F1.x, F1.y);
                mma16816(cf[2], ahi, F2.x, F2.y);
                mma16816(cfl[0], alo, F0.x, F0.y);
                mma16816(cfl[1], alo, F1.x, F1.y);
                mma16816(cfl[2], alo, F2.x, F2.y);
                mma16816(cf[0], ahi, F0.z, F0.w);
                mma16816(cf[1], ahi, F1.z, F1.w);
                mma16816(cf[2], ahi, F2.z, F2.w);
            }
        }
        // merge feat accumulators
#pragma unroll
        for (int nt = 0; nt < 3; nt++)
#pragma unroll
            for (int i = 0; i < 4; i++) cf[nt][i] += cfl[nt][i];

        if ((lane & 3) == 0) {
            float bdv = wsm[784];
            ssig_s[p0] = __expf(cf[2][0] + bdv) * sins_s[p0];
            ssig_s[p1] = __expf(cf[2][2] + bdv) * sins_s[p1];
        }

        // feat A-fragments for c1 (K=16)
        u32 fhi[4], flo[4];
        {
            float bf0 = wsm[768 + kq], bf1 = wsm[768 + kq + 1];
            float bf8 = wsm[768 + kq + 8], bf9 = wsm[768 + kq + 9];
            split_pack(cf[0][0] + bf0, cf[0][1] + bf1, fhi[0], flo[0]);
            split_pack(cf[0][2] + bf0, cf[0][3] + bf1, fhi[1], flo[1]);
            split_pack(cf[1][0] + bf8, cf[1][1] + bf9, fhi[2], flo[2]);
            split_pack(cf[1][2] + bf8, cf[1][3] + bf9, fhi[3], flo[3]);
        }

        // ======== c1 + c2 chained in two N-halves, dual accumulators ========
        float ccol[4] = {0.f, 0.f, 0.f, 0.f};
        float ccoll[4] = {0.f, 0.f, 0.f, 0.f};
#pragma unroll
        for (int h = 0; h < 2; h++) {
            float cc[8][4], ccl[8][4];
#pragma unroll
            for (int nt = 0; nt < 8; nt++)
#pragma unroll
                for (int i = 0; i < 4; i++) { cc[nt][i] = 0.f; ccl[nt][i] = 0.f; }
#pragma unroll
            for (int nt = 0; nt < 8; nt++) {
                uint4 Bf = sB[4864 + (h * 8 + nt) * 32 + lane];
                mma16816(cc[nt], fhi, Bf.x, Bf.y);
                mma16816(ccl[nt], flo, Bf.x, Bf.y);
                mma16816(cc[nt], fhi, Bf.z, Bf.w);
            }
#pragma unroll
            for (int q = 0; q < 4; q++) {
                int ksc = h * 4 + q;
                int col = ksc * 16 + kq;
                float bb0 = shcY_s[col];       // bc1 already folded in
                float bb1 = shcY_s[col + 1];
                float bb8 = shcY_s[col + 8];
                float bb9 = shcY_s[col + 9];
                u32 ahi[4], alo[4];
                split_pack(fmaxf(cc[2 * q][0] + ccl[2 * q][0] + bb0, 0.f),
                           fmaxf(cc[2 * q][1] + ccl[2 * q][1] + bb1, 0.f), ahi[0], alo[0]);
                split_pack(fmaxf(cc[2 * q][2] + ccl[2 * q][2] + bb0, 0.f),
                           fmaxf(cc[2 * q][3] + ccl[2 * q][3] + bb1, 0.f), ahi[1], alo[1]);
                split_pack(fmaxf(cc[2 * q + 1][0] + ccl[2 * q + 1][0] + bb8, 0.f),
                           fmaxf(cc[2 * q + 1][1] + ccl[2 * q + 1][1] + bb9, 0.f),
                           ahi[2], alo[2]);
                split_pack(fmaxf(cc[2 * q + 1][2] + ccl[2 * q + 1][2] + bb8, 0.f),
                           fmaxf(cc[2 * q + 1][3] + ccl[2 * q + 1][3] + bb9, 0.f),
                           ahi[3], alo[3]);
                uint4 B = sB[5376 + ksc * 32 + lane];
                mma16816(ccol, ahi, B.x, B.y);
                mma16816(ccoll, alo, B.x, B.y);
                mma16816(ccol, ahi, B.z, B.w);
            }
        }
        {
            int cq = lane & 3;
            if (cq == 0) {
                float b0v = wsm[785], b1v = wsm[786];
                sc0_s[p0] = fast_sigmoid(ccol[0] + ccoll[0] + b0v);
                sc1_s[p0] = fast_sigmoid(ccol[1] + ccoll[1] + b1v);
                sc0_s[p1] = fast_sigmoid(ccol[2] + ccoll[2] + b0v);
                sc1_s[p1] = fast_sigmoid(ccol[3] + ccoll[3] + b1v);
            } else if (cq == 1) {
                float b2v = wsm[787];
                sc2_s[p0] = fast_sigmoid(ccol[0] + ccoll[0] + b2v);
                sc2_s[p1] = fast_sigmoid(ccol[2] + ccoll[2] + b2v);
            }
        }
        bar_slot(slot);  // (2) ssig, sc0-2 visible

        // ======== integration ========
        float tau = 0.f, tcur = 0.f, sc = 0.f;
        if (lwid < 2) {
            tcur = sts_s[t128];
            float tnext = (t128 < 63) ? sts_s[t128 + 1] : (tf + 1.0f);  // BOOSTER=1.0
            tau = ssig_s[t128] * (tnext - tcur) * dnorm;
            sc = tau;
#pragma unroll
            for (int off = 1; off < 32; off <<= 1) {
                float u = __shfl_up_sync(0xffffffffu, sc, off);
                if (lane >= off) sc += u;
            }
            if (lwid == 0 && lane == 31) sred_s[15] = sc;
        }
        bar_slot(slot);  // (3)
        if (lwid < 2) {
            if (lwid == 1) sc += sred_s[15];
            float excl = sc - tau;
            float wgt = __expf(-excl) * (1.f - __expf(-tau));
            float v0 = wgt * sc0_s[t128];
            float v1 = wgt * sc1_s[t128];
            float v2 = wgt * sc2_s[t128];
            float v3 = wgt;
            float v4 = wgt * tcur;
#pragma unroll
            for (int off = 16; off >= 1; off >>= 1) {
                v0 += __shfl_xor_sync(0xffffffffu, v0, off);
                v1 += __shfl_xor_sync(0xffffffffu, v1, off);
                v2 += __shfl_xor_sync(0xffffffffu, v2, off);
                v3 += __shfl_xor_sync(0xffffffffu, v3, off);
                v4 += __shfl_xor_sync(0xffffffffu, v4, off);
            }
            if (lane == 0) {
                sred_s[lwid * 5 + 0] = v0;
                sred_s[lwid * 5 + 1] = v1;
                sred_s[lwid * 5 + 2] = v2;
                sred_s[lwid * 5 + 3] = v3;
                sred_s[lwid * 5 + 4] = v4;
            }
        }
        bar_slot(slot);  // (4)
        if (t128 < 5) {
            float am = active ? 1.f : 0.f;
            out[ray * 5 + t128] = (sred_s[t128] + sred_s[5 + t128]) * am;
        }
        bar_slot(slot);  // (5) protect reused buffers
    }
}

extern "C" void kernel_launch(void* const* d_in, const int* in_sizes, int n_in,
                              void* d_out, int out_size) {
    const float* rays_o = (const float*)d_in[0];
    const float* rays_d = (const float*)d_in[1];
    const float* aabb   = (const float*)d_in[2];
    const float* W1  = (const float*)d_in[3];
    const float* b1  = (const float*)d_in[4];
    const float* W2  = (const float*)d_in[5];
    const float* b2  = (const float*)d_in[6];
    const float* Wd  = (const float*)d_in[7];
    const float* bd  = (const float*)d_in[8];
    const float* Wf  = (const float*)d_in[9];
    const float* bf  = (const float*)d_in[10];
    const float* Wc1 = (const float*)d_in[11];
    const float* bc1 = (const float*)d_in[12];
    const float* Wc2 = (const float*)d_in[13];
    const float* bc2 = (const float*)d_in[14];
    float* out = (float*)d_out;

    prep_all<<<192, 32>>>(W2, Wf, Wd, Wc1, Wc2);
    size_t smem = 26848 * sizeof(float);  // 107392 B -> 2 blocks/SM
    cudaFuncSetAttribute(radiance_kernel, cudaFuncAttributeMaxDynamicSharedMemorySize,
                         (int)smem);
    radiance_kernel<<<GRID, 256, smem>>>(rays_o, rays_d, aabb, W1, b1, W2, b2, Wd, bd,
                                         Wf, bf, Wc1, bc1, Wc2, bc2, out);
}